// round 12
// baseline (speedup 1.0000x reference)
#include <cuda_runtime.h>
#include <cuda_fp16.h>
#include <cstdint>

#define L_FRAMES 16
#define C_CH     16
#define H_DIM    128
#define W_DIM    256
#define HW       (H_DIM * W_DIM)
#define DECAY_F  0.1f
#define FRAME_BYTES (HW * 32)          // one fp16 channel-last frame = 1 MB

// Channel-last fp16 scratch: [k][h][w][c], 16 MB (single copy)
__device__ __half g_imgT[L_FRAMES * HW * C_CH];

// ---------------------------------------------------------------------------
// Prep: transpose img [k][c][h][w] fp32 -> [k][h][w][c] fp16.
// ---------------------------------------------------------------------------
__global__ void prep_kernel(const float* __restrict__ img) {
    const int kh = blockIdx.x;          // k*H + h
    const int w  = threadIdx.x;         // 0..255
    const int k  = kh >> 7;
    const int h  = kh & (H_DIM - 1);

    __half2 v[8];
#pragma unroll
    for (int c = 0; c < 8; c++) {
        float a = img[((k * C_CH + 2 * c + 0) * H_DIM + h) * W_DIM + w];
        float b = img[((k * C_CH + 2 * c + 1) * H_DIM + h) * W_DIM + w];
        v[c] = __floats2half2_rn(a, b);
    }
    uint4* dst = reinterpret_cast<uint4*>(&g_imgT[((size_t)kh * W_DIM + w) * C_CH]);
    dst[0] = *reinterpret_cast<const uint4*>(&v[0]);
    dst[1] = *reinterpret_cast<const uint4*>(&v[4]);
}

// ---------------------------------------------------------------------------
// Warped accumulation. Flat grid 8192: t = bx & 15, pixel block = bx >> 4.
// 4 lanes per pixel: ch = sub&1 (16B channel half), xh = sub>>1 (x tap).
// Explicit software pipeline: next k-pair's coords+loads issued while the
// current pair is consumed (8 LDG.128 in flight/warp). fp16 pair-accumulate,
// packed f32x2 adds into 64-bit accumulators.
// ---------------------------------------------------------------------------
__global__ void __launch_bounds__(256) sample_kernel(
    const float* __restrict__ cum_flow,   // [k][2][h][w]
    const float* __restrict__ mask,       // [t][k]
    const float* __restrict__ dist,       // [t][k]
    float* __restrict__ out)              // [t][c][h][w]
{
    const int t  = blockIdx.x & 15;
    const int p0 = (blockIdx.x >> 4) << 6;

    __shared__ float  ws[L_FRAMES];
    __shared__ float2 sflow[L_FRAMES * 64];   // [k][px], 8 KB

    if (threadIdx.x < L_FRAMES) {
        int i = t * L_FRAMES + threadIdx.x;
        ws[threadIdx.x] = mask[i] * expf(-DECAY_F * dist[i]);
    }
#pragma unroll
    for (int i = 0; i < 4; i++) {
        const int idx = threadIdx.x + i * 256;      // k*64 + px
        const int kk  = idx >> 6;
        const int px  = idx & 63;
        const float fx = cum_flow[(kk * 2 + 0) * HW + p0 + px];
        const float fy = cum_flow[(kk * 2 + 1) * HW + p0 + px];
        sflow[idx] = make_float2(fx, fy);
    }
    __syncthreads();

    const int tid = threadIdx.x;
    const int sub = tid & 3;
    const int ch  = sub & 1;        // channel half: channels [ch*8, ch*8+8)
    const int xh  = sub >> 1;       // x tap: 0 -> x0, 1 -> x0+1
    const int px  = tid >> 2;       // pixel-in-block 0..63
    const int p   = p0 + px;
    const int h   = p >> 8;
    const int w   = p & (W_DIM - 1);

    const float2 ft = sflow[t * 64 + px];

    const float base_x = (float)w * (2.0f / W_DIM) - 1.0f + (1.0f / W_DIM);
    const float base_y = (float)h * (2.0f / H_DIM) - 1.0f + (1.0f / H_DIM);
    const float Ax = (base_x + ft.x + 1.0f) * (W_DIM * 0.5f) - 0.5f;
    const float Ay = (base_y + ft.y + 1.0f) * (H_DIM * 0.5f) - 0.5f;

    const float sx = xh ? 1.0f : -1.0f;
    const float cx = xh ? 0.0f : 1.0f;

    // packed f32x2 accumulators (acc64[j] = {acc[2j], acc[2j+1]})
    uint64_t acc64[4];
#pragma unroll
    for (int j = 0; j < 4; j++) acc64[j] = 0ull;

    const char* __restrict__ gbase =
        reinterpret_cast<const char*>(g_imgT) + ch * 16;

    // offsets within ONE frame + fp16 weights for frame kk
#define COORDS(kk, OFF0, OFF1, W0H, W1H)                                       \
    unsigned OFF0, OFF1; __half2 W0H, W1H;                                     \
    {                                                                          \
        const float wk  = ws[(kk)];                                            \
        const float2 fk = sflow[(kk) * 64 + px];                               \
        const float ix = fmaf(-(W_DIM * 0.5f), fk.x, Ax);                      \
        const float iy = fmaf(-(H_DIM * 0.5f), fk.y, Ay);                      \
        const int x0 = __float2int_rd(ix);                                     \
        const int y0 = __float2int_rd(iy);                                     \
        const float wx = ix - (float)x0;                                       \
        const float wy = iy - (float)y0;                                       \
        const int x   = (x0 + xh) & (W_DIM - 1);                               \
        const int y0c = min(max(y0, 0), H_DIM - 1);                            \
        const int y1c = min(max(y0 + 1, 0), H_DIM - 1);                        \
        const float xw = fmaf(sx, wx, cx);                                     \
        const float tw = wk * xw;                                              \
        const float w1 = tw * wy;                                              \
        const float w0 = tw - w1;                                              \
        W0H = __float2half2_rn(w0);                                            \
        W1H = __float2half2_rn(w1);                                            \
        const unsigned ox = (unsigned)x << 5;                                  \
        OFF0 = ox + ((unsigned)y0c << 13);                                     \
        OFF1 = ox + ((unsigned)y1c << 13);                                     \
    }

    // pair consume: fp16 4-term combine, one f32x2 packed add per 2 channels
#define CONSUME(UA0, UA1, UB0, UB1, AW0, AW1, BW0, BW1)                        \
    {                                                                          \
        const __half2* ha0 = reinterpret_cast<const __half2*>(&(UA0));         \
        const __half2* ha1 = reinterpret_cast<const __half2*>(&(UA1));         \
        const __half2* hb0 = reinterpret_cast<const __half2*>(&(UB0));         \
        const __half2* hb1 = reinterpret_cast<const __half2*>(&(UB1));         \
        _Pragma("unroll")                                                      \
        for (int j = 0; j < 4; j++) {                                          \
            __half2 s = __hmul2(ha0[j], (AW0));                                \
            s = __hfma2(ha1[j], (AW1), s);                                     \
            s = __hfma2(hb0[j], (BW0), s);                                     \
            s = __hfma2(hb1[j], (BW1), s);                                     \
            const float2 f = __half22float2(s);                                \
            uint64_t fv;                                                       \
            asm("mov.b64 %0, {%1, %2};" : "=l"(fv) : "f"(f.x), "f"(f.y));      \
            asm("add.rn.f32x2 %0, %0, %1;" : "+l"(acc64[j]) : "l"(fv));        \
        }                                                                      \
    }

#define BODY1(kk, GB)                                                          \
    {                                                                          \
        COORDS(kk, o0, o1, w0h, w1h);                                          \
        const uint4 u0 = *reinterpret_cast<const uint4*>((GB) + o0);           \
        const uint4 u1 = *reinterpret_cast<const uint4*>((GB) + o1);           \
        const __half2* h0 = reinterpret_cast<const __half2*>(&u0);             \
        const __half2* h1 = reinterpret_cast<const __half2*>(&u1);             \
        _Pragma("unroll")                                                      \
        for (int j = 0; j < 4; j++) {                                          \
            __half2 s = __hmul2(h0[j], w0h);                                   \
            s = __hfma2(h1[j], w1h, s);                                        \
            const float2 f = __half22float2(s);                                \
            uint64_t fv;                                                       \
            asm("mov.b64 %0, {%1, %2};" : "=l"(fv) : "f"(f.x), "f"(f.y));      \
            asm("add.rn.f32x2 %0, %0, %1;" : "+l"(acc64[j]) : "l"(fv));        \
        }                                                                      \
    }

    int k = 0;
    if (t >= 1) {
        // prologue: prefetch pair (0,1)
        COORDS(0, a0, a1, aw0, aw1);
        uint4 pA0 = *reinterpret_cast<const uint4*>(gbase + a0);
        uint4 pA1 = *reinterpret_cast<const uint4*>(gbase + a1);
        COORDS(1, b0, b1, bw0, bw1);
        uint4 pB0 = *reinterpret_cast<const uint4*>(gbase + FRAME_BYTES + b0);
        uint4 pB1 = *reinterpret_cast<const uint4*>(gbase + FRAME_BYTES + b1);
        __half2 pw0 = aw0, pw1 = aw1, pw2 = bw0, pw3 = bw1;
        const char* gcur = gbase;

#pragma unroll 2
        for (k = 0; k + 3 <= t; k += 2) {
            const char* gnxt = gcur + 2 * FRAME_BYTES;
            // prefetch pair (k+2, k+3)
            COORDS(k + 2, c0, c1, cw0, cw1);
            const uint4 nA0 = *reinterpret_cast<const uint4*>(gnxt + c0);
            const uint4 nA1 = *reinterpret_cast<const uint4*>(gnxt + c1);
            COORDS(k + 3, d0, d1, dw0, dw1);
            const uint4 nB0 = *reinterpret_cast<const uint4*>(gnxt + FRAME_BYTES + d0);
            const uint4 nB1 = *reinterpret_cast<const uint4*>(gnxt + FRAME_BYTES + d1);
            // consume pair (k, k+1)
            CONSUME(pA0, pA1, pB0, pB1, pw0, pw1, pw2, pw3);
            // rotate
            pA0 = nA0; pA1 = nA1; pB0 = nB0; pB1 = nB1;
            pw0 = cw0; pw1 = cw1; pw2 = dw0; pw3 = dw1;
            gcur = gnxt;
        }
        // epilogue: consume last prefetched pair
        CONSUME(pA0, pA1, pB0, pB1, pw0, pw1, pw2, pw3);
        k += 2;
    }
    if (k <= t) BODY1(k, gbase + (unsigned)k * FRAME_BYTES);
#undef BODY1
#undef CONSUME
#undef COORDS

    // unpack accumulators
    float acc[8];
#pragma unroll
    for (int j = 0; j < 4; j++) {
        asm("mov.b64 {%0, %1}, %2;"
            : "=f"(acc[2 * j + 0]), "=f"(acc[2 * j + 1]) : "l"(acc64[j]));
    }

    // merge x-halves: partner lane differs in bit 1 of tid
#pragma unroll
    for (int j = 0; j < 8; j++)
        acc[j] += __shfl_xor_sync(0xffffffffu, acc[j], 2);

    // each lane writes 4 channels: [ch*8 + xh*4, +4)
    const int cbase = (t * C_CH + ch * 8 + xh * 4) * HW + p;
#pragma unroll
    for (int j = 0; j < 4; j++)
        out[cbase + j * HW] = acc[xh * 4 + j];
}

extern "C" void kernel_launch(void* const* d_in, const int* in_sizes, int n_in,
                              void* d_out, int out_size) {
    const float* img      = (const float*)d_in[0];  // (1,16,16,128,256)
    const float* cum_flow = (const float*)d_in[1];  // (1,16,2,128,256)
    const float* mask     = (const float*)d_in[2];  // (16,16)
    const float* dist     = (const float*)d_in[3];  // (16,16)
    float* out            = (float*)d_out;          // (1,16,16,128,256)

    prep_kernel<<<L_FRAMES * H_DIM, W_DIM>>>(img);

    sample_kernel<<<HW / 64 * L_FRAMES, 256>>>(cum_flow, mask, dist, out);
}